// round 6
// baseline (speedup 1.0000x reference)
#include <cuda_runtime.h>
#include <cstdint>

// Problem constants
static constexpr int  Bc  = 2;
static constexpr int  Tc  = 2048;
static constexpr int  Dc  = 1024;
static constexpr int  Hc  = 16;
static constexpr long long OUT_ELEMS = (long long)Bc * Tc * Dc;          // 4194304
static constexpr long long W_ELEMS   = (long long)Bc * Hc * Tc * Tc;     // 134217728

// Scratch (allocation-free rule: __device__ globals)
__device__ float g_q[Bc * Tc * Dc];
__device__ float g_k[Bc * Tc * Dc];
__device__ float g_v[Bc * Tc * Dc];
__device__ float g_attn[Bc * Tc * Dc];
__device__ float g_stats[(size_t)Bc * Hc * Tc * 16 * 2];                 // (m,l) per row per col-tile
__device__ float g_weights[(size_t)Bc * Hc * Tc * Tc];  // fallback if out_size lacks weights

// ---------------------------------------------------------------------------
__device__ __forceinline__ uint32_t f2tf(float x) {
    uint32_t r;
    asm("cvt.rna.tf32.f32 %0, %1;" : "=r"(r) : "f"(x));
    return r;
}

__device__ __forceinline__ void mma_tf32(float* c, const uint32_t* a, const uint32_t* b) {
    asm volatile(
        "mma.sync.aligned.m16n8k8.row.col.f32.tf32.tf32.f32 "
        "{%0,%1,%2,%3}, {%4,%5,%6,%7}, {%8,%9}, {%0,%1,%2,%3};\n"
        : "+f"(c[0]), "+f"(c[1]), "+f"(c[2]), "+f"(c[3])
        : "r"(a[0]), "r"(a[1]), "r"(a[2]), "r"(a[3]), "r"(b[0]), "r"(b[1]));
}

// ---------------------------------------------------------------------------
// Projection GEMM-NT: C[4096,1024] = A[4096,1024] @ W[1024,1024]^T
// grid (8, 32, z); z selects one of 3 independent (A,W,C) triples.
// ---------------------------------------------------------------------------
__global__ __launch_bounds__(256, 2) void proj_nt(
    const float* __restrict__ A0, const float* __restrict__ W0, float* __restrict__ C0,
    const float* __restrict__ A1, const float* __restrict__ W1, float* __restrict__ C1,
    const float* __restrict__ A2, const float* __restrict__ W2, float* __restrict__ C2)
{
    __shared__ uint32_t As2[64 * 72];
    __shared__ uint32_t Bs2[128 * 40];

    const int z = blockIdx.z;
    const float* A = z == 0 ? A0 : (z == 1 ? A1 : A2);
    const float* W = z == 0 ? W0 : (z == 1 ? W1 : W2);
    float*       C = z == 0 ? C0 : (z == 1 ? C1 : C2);

    const float* Ab = A + (long long)blockIdx.y * 128 * 1024;
    const float* Wb = W + (long long)blockIdx.x * 128 * 1024;
    float*       Cb = C + (long long)blockIdx.y * 128 * 1024 + blockIdx.x * 128;

    const int t = threadIdx.x, warp = t >> 5, lane = t & 31;
    const int g = lane >> 2, tg = lane & 3;
    const int m_half = (warp & 1);
    const int n_base = (warp >> 1) * 32;

    float acc[4][4][4];
#pragma unroll
    for (int i = 0; i < 4; i++)
#pragma unroll
        for (int j = 0; j < 4; j++)
#pragma unroll
            for (int r = 0; r < 4; r++) acc[i][j][r] = 0.f;

    for (int k0 = 0; k0 < 1024; k0 += 32) {
#pragma unroll
        for (int i = 0; i < 2; i++) {
            const int idx = i * 256 + t;
            const int pr = idx >> 3, c4 = (idx & 7) * 4;
            const int r = (pr >> 3) * 16 + (pr & 7);
            const float* s0 = Ab + (long long)r * 1024 + k0 + c4;
            float4 lo = *(const float4*)s0;
            float4 hi = *(const float4*)(s0 + 8 * 1024);
            uint32_t* d = &As2[pr * 72 + c4 * 2];
            ((uint2*)d)[0] = make_uint2(f2tf(lo.x), f2tf(hi.x));
            ((uint2*)d)[1] = make_uint2(f2tf(lo.y), f2tf(hi.y));
            ((uint2*)d)[2] = make_uint2(f2tf(lo.z), f2tf(hi.z));
            ((uint2*)d)[3] = make_uint2(f2tf(lo.w), f2tf(hi.w));
        }
#pragma unroll
        for (int i = 0; i < 2; i++) {
            const int idx = i * 256 + t;
            const int n = idx >> 2, c8 = (idx & 3) * 8;
            const float* s0 = Wb + (long long)n * 1024 + k0 + c8;
            float4 lo = *(const float4*)s0;
            float4 hi = *(const float4*)(s0 + 4);
            uint32_t* d = &Bs2[n * 40 + c8];
            ((uint2*)d)[0] = make_uint2(f2tf(lo.x), f2tf(hi.x));
            ((uint2*)d)[1] = make_uint2(f2tf(lo.y), f2tf(hi.y));
            ((uint2*)d)[2] = make_uint2(f2tf(lo.z), f2tf(hi.z));
            ((uint2*)d)[3] = make_uint2(f2tf(lo.w), f2tf(hi.w));
        }
        __syncthreads();

#pragma unroll
        for (int kc = 0; kc < 4; kc++) {
            uint32_t af[4][4];
#pragma unroll
            for (int mi = 0; mi < 4; mi++) {
                const int rowp = (m_half * 4 + mi) * 8 + g;
                uint2 qa = *(const uint2*)&As2[rowp * 72 + (kc * 8 + tg) * 2];
                uint2 qb = *(const uint2*)&As2[rowp * 72 + (kc * 8 + 4 + tg) * 2];
                af[mi][0] = qa.x; af[mi][1] = qa.y; af[mi][2] = qb.x; af[mi][3] = qb.y;
            }
#pragma unroll
            for (int ni = 0; ni < 4; ni++) {
                uint2 bb = *(const uint2*)&Bs2[(n_base + ni * 8 + g) * 40 + kc * 8 + tg * 2];
#pragma unroll
                for (int mi = 0; mi < 4; mi++)
                    mma_tf32(acc[mi][ni], af[mi], &bb.x);
            }
        }
        __syncthreads();
    }

#pragma unroll
    for (int mi = 0; mi < 4; mi++) {
#pragma unroll
        for (int ni = 0; ni < 4; ni++) {
            const int row = m_half * 64 + mi * 16 + g;
            const int col = n_base + ni * 8 + tg * 2;
            *(float2*)(Cb + (long long)row * 1024 + col) =
                make_float2(acc[mi][ni][0], acc[mi][ni][1]);
            *(float2*)(Cb + (long long)(row + 8) * 1024 + col) =
                make_float2(acc[mi][ni][2], acc[mi][ni][3]);
        }
    }
}

// ---------------------------------------------------------------------------
// Scores: one CTA = 128x128 tile of S = (Q K^T)/8 for one (b,h).
// Q and K share one smem region (Q-frags hoisted before K overwrites it).
// Epilogue: per-tile row max m, e = exp(s-m) (kept in regs), row sum l.
// Stores e (not s!) to gmem + (m,l) stats.  smem 39.4 KB -> 2 CTAs/SM.
// ---------------------------------------------------------------------------
static constexpr int SC_SMEM_BYTES = (8704 + 128 * 4 + 128 + 128 * 4) * 4;

__global__ __launch_bounds__(256, 2) void scores_kernel(
    const float* __restrict__ q, const float* __restrict__ k,
    float* __restrict__ eout, float* __restrict__ stats)
{
    extern __shared__ uint32_t sm[];
    uint32_t* Ts  = sm;                       // Q tile, then K tile (stride 68)
    float*    wred = (float*)(sm + 8704);     // [128][4]
    float*    mrow = (float*)(sm + 8704 + 512);
    float*    wsum = (float*)(sm + 8704 + 512 + 128);

    const int bh = blockIdx.z;
    const int b = bh >> 4, h = bh & 15;
    const int qbase = blockIdx.y * 128;
    const int nbase = blockIdx.x * 128;
    const int t = threadIdx.x, warp = t >> 5, lane = t & 31;
    const int g = lane >> 2, tg = lane & 3;
    const int m_half = warp & 1;
    const int n_off  = (warp >> 1) * 32;
    const int nwarp  = warp >> 1;

    const float* qp = q + ((long long)(b * Tc + qbase)) * Dc + h * 64;
    const float* kp = k + ((long long)(b * Tc + nbase)) * Dc + h * 64;

    // ---- load Q tile ----
#pragma unroll
    for (int i = 0; i < 8; i++) {
        const int idx = i * 256 + t;
        const int r = idx >> 4, c4 = (idx & 15) * 4;
        float4 xq = *(const float4*)(qp + (long long)r * Dc + c4);
        uint32_t* dq = &Ts[r * 68 + c4];
        dq[0] = f2tf(xq.x); dq[1] = f2tf(xq.y); dq[2] = f2tf(xq.z); dq[3] = f2tf(xq.w);
    }
    __syncthreads();

    // hoist all Q A-fragments
    uint32_t af[8][4][4];
#pragma unroll
    for (int kc = 0; kc < 8; kc++) {
#pragma unroll
        for (int mi = 0; mi < 4; mi++) {
            const int r0 = (m_half * 64 + mi * 16 + g) * 68;
            af[kc][mi][0] = Ts[r0 + kc * 8 + tg];
            af[kc][mi][1] = Ts[r0 + 8 * 68 + kc * 8 + tg];
            af[kc][mi][2] = Ts[r0 + kc * 8 + 4 + tg];
            af[kc][mi][3] = Ts[r0 + 8 * 68 + kc * 8 + 4 + tg];
        }
    }
    __syncthreads();

    // ---- load K tile into same region ----
#pragma unroll
    for (int i = 0; i < 8; i++) {
        const int idx = i * 256 + t;
        const int r = idx >> 4, c4 = (idx & 15) * 4;
        float4 xk = *(const float4*)(kp + (long long)r * Dc + c4);
        uint32_t* dk = &Ts[r * 68 + c4];
        dk[0] = f2tf(xk.x); dk[1] = f2tf(xk.y); dk[2] = f2tf(xk.z); dk[3] = f2tf(xk.w);
    }
    __syncthreads();

    float sacc[4][4][4];
#pragma unroll
    for (int i = 0; i < 4; i++)
#pragma unroll
        for (int j = 0; j < 4; j++)
#pragma unroll
            for (int r = 0; r < 4; r++) sacc[i][j][r] = 0.f;

#pragma unroll
    for (int kc = 0; kc < 8; kc++) {
        uint32_t bf[4][2];
#pragma unroll
        for (int ni = 0; ni < 4; ni++) {
            const int n0 = (n_off + ni * 8 + g) * 68;
            bf[ni][0] = Ts[n0 + kc * 8 + tg];
            bf[ni][1] = Ts[n0 + kc * 8 + 4 + tg];
        }
#pragma unroll
        for (int mi = 0; mi < 4; mi++)
#pragma unroll
            for (int ni = 0; ni < 4; ni++)
                mma_tf32(sacc[mi][ni], af[kc][mi], bf[ni]);
    }

    // scale
#pragma unroll
    for (int mi = 0; mi < 4; mi++)
#pragma unroll
        for (int ni = 0; ni < 4; ni++)
#pragma unroll
            for (int r = 0; r < 4; r++) sacc[mi][ni][r] *= 0.125f;

    // ---- per-tile row max ----
#pragma unroll
    for (int mi = 0; mi < 4; mi++) {
        float v0 = -1e30f, v1 = -1e30f;
#pragma unroll
        for (int ni = 0; ni < 4; ni++) {
            v0 = fmaxf(v0, fmaxf(sacc[mi][ni][0], sacc[mi][ni][1]));
            v1 = fmaxf(v1, fmaxf(sacc[mi][ni][2], sacc[mi][ni][3]));
        }
        v0 = fmaxf(v0, __shfl_xor_sync(0xffffffffu, v0, 1));
        v0 = fmaxf(v0, __shfl_xor_sync(0xffffffffu, v0, 2));
        v1 = fmaxf(v1, __shfl_xor_sync(0xffffffffu, v1, 1));
        v1 = fmaxf(v1, __shfl_xor_sync(0xffffffffu, v1, 2));
        if (tg == 0) {
            wred[(m_half * 64 + mi * 16 + g) * 4 + nwarp]     = v0;
            wred[(m_half * 64 + mi * 16 + 8 + g) * 4 + nwarp] = v1;
        }
    }
    __syncthreads();
    if (t < 128) {
        mrow[t] = fmaxf(fmaxf(wred[t * 4], wred[t * 4 + 1]),
                        fmaxf(wred[t * 4 + 2], wred[t * 4 + 3]));
    }
    __syncthreads();

    // ---- e = exp(s - m) (kept in sacc), row sum ----
#pragma unroll
    for (int mi = 0; mi < 4; mi++) {
        const float m0 = mrow[m_half * 64 + mi * 16 + g];
        const float m1 = mrow[m_half * 64 + mi * 16 + 8 + g];
        float s0 = 0.f, s1 = 0.f;
#pragma unroll
        for (int ni = 0; ni < 4; ni++) {
            sacc[mi][ni][0] = __expf(sacc[mi][ni][0] - m0);
            sacc[mi][ni][1] = __expf(sacc[mi][ni][1] - m0);
            sacc[mi][ni][2] = __expf(sacc[mi][ni][2] - m1);
            sacc[mi][ni][3] = __expf(sacc[mi][ni][3] - m1);
            s0 += sacc[mi][ni][0] + sacc[mi][ni][1];
            s1 += sacc[mi][ni][2] + sacc[mi][ni][3];
        }
        s0 += __shfl_xor_sync(0xffffffffu, s0, 1);
        s0 += __shfl_xor_sync(0xffffffffu, s0, 2);
        s1 += __shfl_xor_sync(0xffffffffu, s1, 1);
        s1 += __shfl_xor_sync(0xffffffffu, s1, 2);
        if (tg == 0) {
            wsum[(m_half * 64 + mi * 16 + g) * 4 + nwarp]     = s0;
            wsum[(m_half * 64 + mi * 16 + 8 + g) * 4 + nwarp] = s1;
        }
    }
    __syncthreads();
    if (t < 128) {
        float l = wsum[t * 4] + wsum[t * 4 + 1] + wsum[t * 4 + 2] + wsum[t * 4 + 3];
        float2* st = (float2*)(stats + (((long long)bh * Tc + qbase + t) * 16 + blockIdx.x) * 2);
        *st = make_float2(mrow[t], l);
    }

    // ---- store e tile ----
#pragma unroll
    for (int mi = 0; mi < 4; mi++) {
#pragma unroll
        for (int ni = 0; ni < 4; ni++) {
            const int row = m_half * 64 + mi * 16 + g;
            const int col = nbase + n_off + ni * 8 + tg * 2;
            float* w0 = eout + ((long long)bh * Tc + qbase + row) * Tc + col;
            *(float2*)w0 = make_float2(sacc[mi][ni][0], sacc[mi][ni][1]);
            *(float2*)(w0 + 8 * Tc) = make_float2(sacc[mi][ni][2], sacc[mi][ni][3]);
        }
    }
}

// ---------------------------------------------------------------------------
// softmax+PV: one CTA = 128 query rows of one (b,h).
// w = e_stored * rsc[row][jtile] where rsc = exp(m_j - m)/l.  No expf in the
// stream loop.  O = W @ V accumulated with MMA.  smem 61.4 KB -> 2 CTAs/SM.
// smem (words): Pp[128*68] @0, Vs[64*72] @8704, rsc[128*16] @13312
// ---------------------------------------------------------------------------
static constexpr int SPV_SMEM_BYTES = (8704 + 4608 + 2048) * 4;

__global__ __launch_bounds__(256, 2) void softmax_pv(
    const float* __restrict__ v, float* __restrict__ w,
    const float* __restrict__ stats, float* __restrict__ attn)
{
    extern __shared__ uint32_t sm[];
    uint32_t* Pp = sm;
    uint32_t* Vs = sm + 8704;
    float*    rsc = (float*)(sm + 13312);     // [128][16]

    const int bh = blockIdx.z;
    const int b = bh >> 4, h = bh & 15;
    const int qbase = blockIdx.y * 128;
    const int t = threadIdx.x, warp = t >> 5, lane = t & 31;
    const int g = lane >> 2, tg = lane & 3;

    const float* vp = v + ((long long)b * Tc) * Dc + h * 64;
    float* wb = w + ((long long)bh * Tc + qbase) * Tc;

    // per-row final stats -> 16 per-tile rescale factors
    if (t < 128) {
        const float2* st = (const float2*)(stats + (((long long)bh * Tc + qbase + t) * 16) * 2);
        float2 sl[16];
        float m = -1e30f;
#pragma unroll
        for (int j = 0; j < 16; j++) { sl[j] = st[j]; m = fmaxf(m, sl[j].x); }
        float l = 0.f;
#pragma unroll
        for (int j = 0; j < 16; j++) l += sl[j].y * __expf(sl[j].x - m);
        const float inv = 1.0f / l;
#pragma unroll
        for (int j = 0; j < 16; j++) rsc[t * 16 + j] = __expf(sl[j].x - m) * inv;
    }
    __syncthreads();

    float oacc[8][4];
#pragma unroll
    for (int nf = 0; nf < 8; nf++)
#pragma unroll
        for (int r = 0; r < 4; r++) oacc[nf][r] = 0.f;

    for (int sub = 0; sub < 32; sub++) {
        const int j = sub >> 1;
        // V subtile (64 seq rows x 64 dk), stride 72
#pragma unroll
        for (int i = 0; i < 4; i++) {
            const int idx = i * 256 + t;
            const int kk = idx >> 4, c4 = (idx & 15) * 4;
            float4 x = *(const float4*)(vp + (long long)(sub * 64 + kk) * Dc + c4);
            uint32_t* d = &Vs[kk * 72 + c4];
            d[0] = f2tf(x.x); d[1] = f2tf(x.y); d[2] = f2tf(x.z); d[3] = f2tf(x.w);
        }
        // stream e -> normalized W (in place) + tf32 P to smem
#pragma unroll
        for (int i = 0; i < 8; i++) {
            const int idx = i * 256 + t;
            const int row = idx >> 4, c4 = (idx & 15) * 4;
            float* gp = wb + (long long)row * Tc + sub * 64 + c4;
            float4 e = *(const float4*)gp;
            const float sc = rsc[row * 16 + j];
            float4 p = make_float4(e.x * sc, e.y * sc, e.z * sc, e.w * sc);
            *(float4*)gp = p;
            uint32_t* d = &Pp[row * 68 + c4];
            d[0] = f2tf(p.x); d[1] = f2tf(p.y); d[2] = f2tf(p.z); d[3] = f2tf(p.w);
        }
        __syncthreads();

        // O += P @ V
#pragma unroll
        for (int kc = 0; kc < 8; kc++) {
            const int r0 = (warp * 16 + g) * 68;
            uint32_t a[4];
            a[0] = Pp[r0 + kc * 8 + tg];
            a[1] = Pp[r0 + 8 * 68 + kc * 8 + tg];
            a[2] = Pp[r0 + kc * 8 + 4 + tg];
            a[3] = Pp[r0 + 8 * 68 + kc * 8 + 4 + tg];
#pragma unroll
            for (int nf = 0; nf < 8; nf++) {
                uint32_t bfr[2];
                bfr[0] = Vs[(kc * 8 + tg) * 72 + nf * 8 + g];
                bfr[1] = Vs[(kc * 8 + 4 + tg) * 72 + nf * 8 + g];
                mma_tf32(oacc[nf], a, bfr);
            }
        }
        __syncthreads();
    }

    // write O into attn buffer [B,T,D]
    float* op0 = attn + ((long long)(b * Tc + qbase + warp * 16 + g)) * Dc + h * 64;
    float* op1 = op0 + 8 * Dc;
#pragma unroll
    for (int nf = 0; nf < 8; nf++) {
        const int c = nf * 8 + tg * 2;
        *(float2*)(op0 + c) = make_float2(oacc[nf][0], oacc[nf][1]);
        *(float2*)(op1 + c) = make_float2(oacc[nf][2], oacc[nf][3]);
    }
}

// ---------------------------------------------------------------------------
extern "C" void kernel_launch(void* const* d_in, const int* /*in_sizes*/, int /*n_in*/,
                              void* d_out, int out_size)
{
    const float* query = (const float*)d_in[0];
    const float* key_i = (const float*)d_in[1];
    const float* value = (const float*)d_in[2];
    const float* Wq    = (const float*)d_in[3];
    const float* Wk    = (const float*)d_in[4];
    const float* Wv    = (const float*)d_in[5];
    const float* Wo    = (const float*)d_in[6];
    float* out = (float*)d_out;

    float *q, *k, *v, *attn, *stats, *wbuf;
    cudaGetSymbolAddress((void**)&q,     g_q);
    cudaGetSymbolAddress((void**)&k,     g_k);
    cudaGetSymbolAddress((void**)&v,     g_v);
    cudaGetSymbolAddress((void**)&attn,  g_attn);
    cudaGetSymbolAddress((void**)&stats, g_stats);
    if ((long long)out_size >= OUT_ELEMS + W_ELEMS) {
        wbuf = out + OUT_ELEMS;                 // tuple-concat output: [out | weights]
    } else {
        cudaGetSymbolAddress((void**)&wbuf, g_weights);
    }

    cudaFuncSetAttribute(scores_kernel, cudaFuncAttributeMaxDynamicSharedMemorySize,
                         SC_SMEM_BYTES);
    cudaFuncSetAttribute(softmax_pv, cudaFuncAttributeMaxDynamicSharedMemorySize,
                         SPV_SMEM_BYTES);

    // 1) Q/K/V projections in one launch
    proj_nt<<<dim3(8, 32, 3), 256>>>(query, Wq, q, key_i, Wk, k, value, Wv, v);

    // 2) e = exp(s - m_tile) + per-tile stats
    scores_kernel<<<dim3(16, 16, 32), 256, SC_SMEM_BYTES>>>(q, k, wbuf, stats);

    // 3) rescale to final weights (in place) + PV
    softmax_pv<<<dim3(1, 16, 32), 256, SPV_SMEM_BYTES>>>(v, wbuf, stats, attn);

    // 4) out = attn @ Wo^T
    proj_nt<<<dim3(8, 32, 1), 256>>>(attn, Wo, out, attn, Wo, out, attn, Wo, out);
}

// round 8
// speedup vs baseline: 1.3768x; 1.3768x over previous
#include <cuda_runtime.h>
#include <cstdint>

// Problem constants
static constexpr int  Bc  = 2;
static constexpr int  Tc  = 2048;
static constexpr int  Dc  = 1024;
static constexpr int  Hc  = 16;
static constexpr long long OUT_ELEMS = (long long)Bc * Tc * Dc;          // 4194304
static constexpr long long W_ELEMS   = (long long)Bc * Hc * Tc * Tc;     // 134217728

// Scratch (allocation-free rule: __device__ globals)
__device__ float g_q[Bc * Tc * Dc];
__device__ float g_k[Bc * Tc * Dc];
__device__ float g_v[Bc * Tc * Dc];
__device__ float g_attn[Bc * Tc * Dc];
__device__ float g_stats[(size_t)Bc * Hc * Tc * 16 * 2];                 // (m,l) per row per col-tile
__device__ float g_weights[(size_t)Bc * Hc * Tc * Tc];  // fallback if out_size lacks weights

// ---------------------------------------------------------------------------
__device__ __forceinline__ uint32_t f2tf(float x) {
    uint32_t r;
    asm("cvt.rna.tf32.f32 %0, %1;" : "=r"(r) : "f"(x));
    return r;
}

__device__ __forceinline__ void mma_tf32(float* c, const uint32_t* a, const uint32_t* b) {
    asm volatile(
        "mma.sync.aligned.m16n8k8.row.col.f32.tf32.tf32.f32 "
        "{%0,%1,%2,%3}, {%4,%5,%6,%7}, {%8,%9}, {%0,%1,%2,%3};\n"
        : "+f"(c[0]), "+f"(c[1]), "+f"(c[2]), "+f"(c[3])
        : "r"(a[0]), "r"(a[1]), "r"(a[2]), "r"(a[3]), "r"(b[0]), "r"(b[1]));
}

// ---------------------------------------------------------------------------
// Projection GEMM-NT: C[4096,1024] = A[4096,1024] @ W[1024,1024]^T
// grid (8, 32, z); z selects one of 3 independent (A,W,C) triples.
// ---------------------------------------------------------------------------
__global__ __launch_bounds__(256, 2) void proj_nt(
    const float* __restrict__ A0, const float* __restrict__ W0, float* __restrict__ C0,
    const float* __restrict__ A1, const float* __restrict__ W1, float* __restrict__ C1,
    const float* __restrict__ A2, const float* __restrict__ W2, float* __restrict__ C2)
{
    __shared__ uint32_t As2[64 * 72];
    __shared__ uint32_t Bs2[128 * 40];

    const int z = blockIdx.z;
    const float* A = z == 0 ? A0 : (z == 1 ? A1 : A2);
    const float* W = z == 0 ? W0 : (z == 1 ? W1 : W2);
    float*       C = z == 0 ? C0 : (z == 1 ? C1 : C2);

    const float* Ab = A + (long long)blockIdx.y * 128 * 1024;
    const float* Wb = W + (long long)blockIdx.x * 128 * 1024;
    float*       Cb = C + (long long)blockIdx.y * 128 * 1024 + blockIdx.x * 128;

    const int t = threadIdx.x, warp = t >> 5, lane = t & 31;
    const int g = lane >> 2, tg = lane & 3;
    const int m_half = (warp & 1);
    const int n_base = (warp >> 1) * 32;

    float acc[4][4][4];
#pragma unroll
    for (int i = 0; i < 4; i++)
#pragma unroll
        for (int j = 0; j < 4; j++)
#pragma unroll
            for (int r = 0; r < 4; r++) acc[i][j][r] = 0.f;

    for (int k0 = 0; k0 < 1024; k0 += 32) {
#pragma unroll
        for (int i = 0; i < 2; i++) {
            const int idx = i * 256 + t;
            const int pr = idx >> 3, c4 = (idx & 7) * 4;
            const int r = (pr >> 3) * 16 + (pr & 7);
            const float* s0 = Ab + (long long)r * 1024 + k0 + c4;
            float4 lo = *(const float4*)s0;
            float4 hi = *(const float4*)(s0 + 8 * 1024);
            uint32_t* d = &As2[pr * 72 + c4 * 2];
            ((uint2*)d)[0] = make_uint2(f2tf(lo.x), f2tf(hi.x));
            ((uint2*)d)[1] = make_uint2(f2tf(lo.y), f2tf(hi.y));
            ((uint2*)d)[2] = make_uint2(f2tf(lo.z), f2tf(hi.z));
            ((uint2*)d)[3] = make_uint2(f2tf(lo.w), f2tf(hi.w));
        }
#pragma unroll
        for (int i = 0; i < 2; i++) {
            const int idx = i * 256 + t;
            const int n = idx >> 2, c8 = (idx & 3) * 8;
            const float* s0 = Wb + (long long)n * 1024 + k0 + c8;
            float4 lo = *(const float4*)s0;
            float4 hi = *(const float4*)(s0 + 4);
            uint32_t* d = &Bs2[n * 40 + c8];
            ((uint2*)d)[0] = make_uint2(f2tf(lo.x), f2tf(hi.x));
            ((uint2*)d)[1] = make_uint2(f2tf(lo.y), f2tf(hi.y));
            ((uint2*)d)[2] = make_uint2(f2tf(lo.z), f2tf(hi.z));
            ((uint2*)d)[3] = make_uint2(f2tf(lo.w), f2tf(hi.w));
        }
        __syncthreads();

#pragma unroll
        for (int kc = 0; kc < 4; kc++) {
            uint32_t af[4][4];
#pragma unroll
            for (int mi = 0; mi < 4; mi++) {
                const int rowp = (m_half * 4 + mi) * 8 + g;
                uint2 qa = *(const uint2*)&As2[rowp * 72 + (kc * 8 + tg) * 2];
                uint2 qb = *(const uint2*)&As2[rowp * 72 + (kc * 8 + 4 + tg) * 2];
                af[mi][0] = qa.x; af[mi][1] = qa.y; af[mi][2] = qb.x; af[mi][3] = qb.y;
            }
#pragma unroll
            for (int ni = 0; ni < 4; ni++) {
                uint2 bb = *(const uint2*)&Bs2[(n_base + ni * 8 + g) * 40 + kc * 8 + tg * 2];
#pragma unroll
                for (int mi = 0; mi < 4; mi++)
                    mma_tf32(acc[mi][ni], af[mi], &bb.x);
            }
        }
        __syncthreads();
    }

#pragma unroll
    for (int mi = 0; mi < 4; mi++) {
#pragma unroll
        for (int ni = 0; ni < 4; ni++) {
            const int row = m_half * 64 + mi * 16 + g;
            const int col = n_base + ni * 8 + tg * 2;
            *(float2*)(Cb + (long long)row * 1024 + col) =
                make_float2(acc[mi][ni][0], acc[mi][ni][1]);
            *(float2*)(Cb + (long long)(row + 8) * 1024 + col) =
                make_float2(acc[mi][ni][2], acc[mi][ni][3]);
        }
    }
}

// ---------------------------------------------------------------------------
// Scores: one CTA = 128x128 tile of S = (Q K^T)/8 for one (b,h).
// R4 structure (separate Q/K smem, per-kc fragment loads) + e-store epilogue:
// per-tile row max m, e = exp(s-m) kept in regs, row sum l; stores e + (m,l).
// ---------------------------------------------------------------------------
static constexpr int SC_SMEM_BYTES = (17408 + 512 + 128 + 512) * 4;   // 74240 B

__global__ __launch_bounds__(256, 2) void scores_kernel(
    const float* __restrict__ q, const float* __restrict__ k,
    float* __restrict__ eout, float* __restrict__ stats)
{
    extern __shared__ uint32_t sm[];
    uint32_t* Qs  = sm;                        // [128][68]
    uint32_t* Ks  = sm + 8704;                 // [128][68]
    float*    wred = (float*)(sm + 17408);     // [128][4]
    float*    mrow = (float*)(sm + 17920);     // [128]
    float*    wsum = (float*)(sm + 18048);     // [128][4]

    const int bh = blockIdx.z;
    const int b = bh >> 4, h = bh & 15;
    const int qbase = blockIdx.y * 128;
    const int nbase = blockIdx.x * 128;
    const int t = threadIdx.x, warp = t >> 5, lane = t & 31;
    const int g = lane >> 2, tg = lane & 3;
    const int m_half = warp & 1;
    const int n_off  = (warp >> 1) * 32;
    const int nwarp  = warp >> 1;

    const float* qp = q + ((long long)(b * Tc + qbase)) * Dc + h * 64;
    const float* kp = k + ((long long)(b * Tc + nbase)) * Dc + h * 64;

    // load Q and K tiles (interleaved -> high MLP)
#pragma unroll
    for (int i = 0; i < 8; i++) {
        const int idx = i * 256 + t;
        const int r = idx >> 4, c4 = (idx & 15) * 4;
        float4 xq = *(const float4*)(qp + (long long)r * Dc + c4);
        float4 xk = *(const float4*)(kp + (long long)r * Dc + c4);
        uint32_t* dq = &Qs[r * 68 + c4];
        dq[0] = f2tf(xq.x); dq[1] = f2tf(xq.y); dq[2] = f2tf(xq.z); dq[3] = f2tf(xq.w);
        uint32_t* dk = &Ks[r * 68 + c4];
        dk[0] = f2tf(xk.x); dk[1] = f2tf(xk.y); dk[2] = f2tf(xk.z); dk[3] = f2tf(xk.w);
    }
    __syncthreads();

    float sacc[4][4][4];
#pragma unroll
    for (int i = 0; i < 4; i++)
#pragma unroll
        for (int j = 0; j < 4; j++)
#pragma unroll
            for (int r = 0; r < 4; r++) sacc[i][j][r] = 0.f;

#pragma unroll
    for (int kc = 0; kc < 8; kc++) {
        uint32_t af[4][4], bf[4][2];
#pragma unroll
        for (int mi = 0; mi < 4; mi++) {
            const int r0 = (m_half * 64 + mi * 16 + g) * 68;
            af[mi][0] = Qs[r0 + kc * 8 + tg];
            af[mi][1] = Qs[r0 + 8 * 68 + kc * 8 + tg];
            af[mi][2] = Qs[r0 + kc * 8 + 4 + tg];
            af[mi][3] = Qs[r0 + 8 * 68 + kc * 8 + 4 + tg];
        }
#pragma unroll
        for (int ni = 0; ni < 4; ni++) {
            const int n0 = (n_off + ni * 8 + g) * 68;
            bf[ni][0] = Ks[n0 + kc * 8 + tg];
            bf[ni][1] = Ks[n0 + kc * 8 + 4 + tg];
        }
#pragma unroll
        for (int mi = 0; mi < 4; mi++)
#pragma unroll
            for (int ni = 0; ni < 4; ni++)
                mma_tf32(sacc[mi][ni], af[mi], bf[ni]);
    }

    // scale
#pragma unroll
    for (int mi = 0; mi < 4; mi++)
#pragma unroll
        for (int ni = 0; ni < 4; ni++)
#pragma unroll
            for (int r = 0; r < 4; r++) sacc[mi][ni][r] *= 0.125f;

    // per-tile row max
#pragma unroll
    for (int mi = 0; mi < 4; mi++) {
        float v0 = -1e30f, v1 = -1e30f;
#pragma unroll
        for (int ni = 0; ni < 4; ni++) {
            v0 = fmaxf(v0, fmaxf(sacc[mi][ni][0], sacc[mi][ni][1]));
            v1 = fmaxf(v1, fmaxf(sacc[mi][ni][2], sacc[mi][ni][3]));
        }
        v0 = fmaxf(v0, __shfl_xor_sync(0xffffffffu, v0, 1));
        v0 = fmaxf(v0, __shfl_xor_sync(0xffffffffu, v0, 2));
        v1 = fmaxf(v1, __shfl_xor_sync(0xffffffffu, v1, 1));
        v1 = fmaxf(v1, __shfl_xor_sync(0xffffffffu, v1, 2));
        if (tg == 0) {
            wred[(m_half * 64 + mi * 16 + g) * 4 + nwarp]     = v0;
            wred[(m_half * 64 + mi * 16 + 8 + g) * 4 + nwarp] = v1;
        }
    }
    __syncthreads();
    if (t < 128) {
        mrow[t] = fmaxf(fmaxf(wred[t * 4], wred[t * 4 + 1]),
                        fmaxf(wred[t * 4 + 2], wred[t * 4 + 3]));
    }
    __syncthreads();

    // e = exp(s - m) (kept in sacc), row sum
#pragma unroll
    for (int mi = 0; mi < 4; mi++) {
        const float m0 = mrow[m_half * 64 + mi * 16 + g];
        const float m1 = mrow[m_half * 64 + mi * 16 + 8 + g];
        float s0 = 0.f, s1 = 0.f;
#pragma unroll
        for (int ni = 0; ni < 4; ni++) {
            sacc[mi][ni][0] = __expf(sacc[mi][ni][0] - m0);
            sacc[mi][ni][1] = __expf(sacc[mi][ni][1] - m0);
            sacc[mi][ni][2] = __expf(sacc[mi][ni][2] - m1);
            sacc[mi][ni][3] = __expf(sacc[mi][ni][3] - m1);
            s0 += sacc[mi][ni][0] + sacc[mi][ni][1];
            s1 += sacc[mi][ni][2] + sacc[mi][ni][3];
        }
        s0 += __shfl_xor_sync(0xffffffffu, s0, 1);
        s0 += __shfl_xor_sync(0xffffffffu, s0, 2);
        s1 += __shfl_xor_sync(0xffffffffu, s1, 1);
        s1 += __shfl_xor_sync(0xffffffffu, s1, 2);
        if (tg == 0) {
            wsum[(m_half * 64 + mi * 16 + g) * 4 + nwarp]     = s0;
            wsum[(m_half * 64 + mi * 16 + 8 + g) * 4 + nwarp] = s1;
        }
    }
    __syncthreads();
    if (t < 128) {
        float l = wsum[t * 4] + wsum[t * 4 + 1] + wsum[t * 4 + 2] + wsum[t * 4 + 3];
        float2* st = (float2*)(stats + (((long long)bh * Tc + qbase + t) * 16 + blockIdx.x) * 2);
        *st = make_float2(mrow[t], l);
    }

    // store e tile
#pragma unroll
    for (int mi = 0; mi < 4; mi++) {
#pragma unroll
        for (int ni = 0; ni < 4; ni++) {
            const int row = m_half * 64 + mi * 16 + g;
            const int col = nbase + n_off + ni * 8 + tg * 2;
            float* w0 = eout + ((long long)bh * Tc + qbase + row) * Tc + col;
            *(float2*)w0 = make_float2(sacc[mi][ni][0], sacc[mi][ni][1]);
            *(float2*)(w0 + 8 * Tc) = make_float2(sacc[mi][ni][2], sacc[mi][ni][3]);
        }
    }
}

// ---------------------------------------------------------------------------
// softmax+PV (software-pipelined): one CTA = 128 query rows of one (b,h).
// Iter sub: stash prefetched regs to smem (w STG + tf32 P/V STS), sync,
// prefetch sub+1 (LDGs overlap MMA), MMA, sync.  Exp-free stream loop.
// smem (words): Pp[128*68] @0, Vs[64*72] @8704, rsc[128*16] @13312
// ---------------------------------------------------------------------------
static constexpr int SPV_SMEM_BYTES = (8704 + 4608 + 2048) * 4;   // 61440 B

__global__ __launch_bounds__(256, 2) void softmax_pv(
    const float* __restrict__ v, float* __restrict__ w,
    const float* __restrict__ stats, float* __restrict__ attn)
{
    extern __shared__ uint32_t sm[];
    uint32_t* Pp = sm;
    uint32_t* Vs = sm + 8704;
    float*    rsc = (float*)(sm + 13312);     // [128][16]

    const int bh = blockIdx.z;
    const int b = bh >> 4, h = bh & 15;
    const int qbase = blockIdx.y * 128;
    const int t = threadIdx.x, warp = t >> 5, lane = t & 31;
    const int g = lane >> 2, tg = lane & 3;

    const float* vp = v + ((long long)b * Tc) * Dc + h * 64;
    float* wb = w + ((long long)bh * Tc + qbase) * Tc;

    // per-row final stats -> 16 per-tile rescale factors
    if (t < 128) {
        const float2* st = (const float2*)(stats + (((long long)bh * Tc + qbase + t) * 16) * 2);
        float2 sl[16];
        float m = -1e30f;
#pragma unroll
        for (int j = 0; j < 16; j++) { sl[j] = st[j]; m = fmaxf(m, sl[j].x); }
        float l = 0.f;
#pragma unroll
        for (int j = 0; j < 16; j++) l += sl[j].y * __expf(sl[j].x - m);
        const float inv = 1.0f / l;
#pragma unroll
        for (int j = 0; j < 16; j++) rsc[t * 16 + j] = __expf(sl[j].x - m) * inv;
    }

    // per-thread fixed addressing for the streamed strips
    const int erow = t >> 4;                  // 0..15 (x8 strips of 16 rows)
    const int ec4  = (t & 15) * 4;
    const int vrow = t >> 4;                  // 0..15 (x4 strips of 16 rows)
    const int vc4  = (t & 15) * 4;

    float4 pe[8], pv4[4];
    // prefetch sub = 0
#pragma unroll
    for (int i = 0; i < 4; i++)
        pv4[i] = *(const float4*)(vp + (long long)(i * 16 + vrow) * Dc + vc4);
#pragma unroll
    for (int i = 0; i < 8; i++)
        pe[i] = *(const float4*)(wb + (long long)(i * 16 + erow) * Tc + ec4);

    __syncthreads();   // rsc ready

    float oacc[8][4];
#pragma unroll
    for (int nf = 0; nf < 8; nf++)
#pragma unroll
        for (int r = 0; r < 4; r++) oacc[nf][r] = 0.f;

    for (int sub = 0; sub < 32; sub++) {
        const int j = sub >> 1;
        // ---- stash phase: V tf32 -> smem, e -> normalized w (STG) + tf32 P -> smem
#pragma unroll
        for (int i = 0; i < 4; i++) {
            uint32_t* d = &Vs[(i * 16 + vrow) * 72 + vc4];
            d[0] = f2tf(pv4[i].x); d[1] = f2tf(pv4[i].y);
            d[2] = f2tf(pv4[i].z); d[3] = f2tf(pv4[i].w);
        }
#pragma unroll
        for (int i = 0; i < 8; i++) {
            const int row = i * 16 + erow;
            const float sc = rsc[row * 16 + j];
            float4 p = make_float4(pe[i].x * sc, pe[i].y * sc, pe[i].z * sc, pe[i].w * sc);
            *(float4*)(wb + (long long)row * Tc + sub * 64 + ec4) = p;
            uint32_t* d = &Pp[row * 68 + ec4];
            d[0] = f2tf(p.x); d[1] = f2tf(p.y); d[2] = f2tf(p.z); d[3] = f2tf(p.w);
        }
        __syncthreads();

        // ---- prefetch sub+1 (LDGs overlap the MMA below)
        if (sub < 31) {
            const float* vpn = vp + (long long)(sub + 1) * 64 * Dc;
            const float* wbn = wb + (sub + 1) * 64;
#pragma unroll
            for (int i = 0; i < 4; i++)
                pv4[i] = *(const float4*)(vpn + (long long)(i * 16 + vrow) * Dc + vc4);
#pragma unroll
            for (int i = 0; i < 8; i++)
                pe[i] = *(const float4*)(wbn + (long long)(i * 16 + erow) * Tc + ec4);
        }

        // ---- O += P @ V
#pragma unroll
        for (int kc = 0; kc < 8; kc++) {
            const int r0 = (warp * 16 + g) * 68;
            uint32_t a[4];
            a[0] = Pp[r0 + kc * 8 + tg];
            a[1] = Pp[r0 + 8 * 68 + kc * 8 + tg];
            a[2] = Pp[r0 + kc * 8 + 4 + tg];
            a[3] = Pp[r0 + 8 * 68 + kc * 8 + 4 + tg];
#pragma unroll
            for (int nf = 0; nf < 8; nf++) {
                uint32_t bfr[2];
                bfr[0] = Vs[(kc * 8 + tg) * 72 + nf * 8 + g];
                bfr[1] = Vs[(kc * 8 + 4 + tg) * 72 + nf * 8 + g];
                mma_tf32(oacc[nf], a, bfr);
            }
        }
        __syncthreads();
    }

    // write O into attn buffer [B,T,D]
    float* op0 = attn + ((long long)(b * Tc + qbase + warp * 16 + g)) * Dc + h * 64;
    float* op1 = op0 + 8 * Dc;
#pragma unroll
    for (int nf = 0; nf < 8; nf++) {
        const int c = nf * 8 + tg * 2;
        *(float2*)(op0 + c) = make_float2(oacc[nf][0], oacc[nf][1]);
        *(float2*)(op1 + c) = make_float2(oacc[nf][2], oacc[nf][3]);
    }
}

// ---------------------------------------------------------------------------
extern "C" void kernel_launch(void* const* d_in, const int* /*in_sizes*/, int /*n_in*/,
                              void* d_out, int out_size)
{
    const float* query = (const float*)d_in[0];
    const float* key_i = (const float*)d_in[1];
    const float* value = (const float*)d_in[2];
    const float* Wq    = (const float*)d_in[3];
    const float* Wk    = (const float*)d_in[4];
    const float* Wv    = (const float*)d_in[5];
    const float* Wo    = (const float*)d_in[6];
    float* out = (float*)d_out;

    float *q, *k, *v, *attn, *stats, *wbuf;
    cudaGetSymbolAddress((void**)&q,     g_q);
    cudaGetSymbolAddress((void**)&k,     g_k);
    cudaGetSymbolAddress((void**)&v,     g_v);
    cudaGetSymbolAddress((void**)&attn,  g_attn);
    cudaGetSymbolAddress((void**)&stats, g_stats);
    if ((long long)out_size >= OUT_ELEMS + W_ELEMS) {
        wbuf = out + OUT_ELEMS;                 // tuple-concat output: [out | weights]
    } else {
        cudaGetSymbolAddress((void**)&wbuf, g_weights);
    }

    cudaFuncSetAttribute(scores_kernel, cudaFuncAttributeMaxDynamicSharedMemorySize,
                         SC_SMEM_BYTES);
    cudaFuncSetAttribute(softmax_pv, cudaFuncAttributeMaxDynamicSharedMemorySize,
                         SPV_SMEM_BYTES);

    // 1) Q/K/V projections in one launch
    proj_nt<<<dim3(8, 32, 3), 256>>>(query, Wq, q, key_i, Wk, k, value, Wv, v);

    // 2) e = exp(s - m_tile) + per-tile stats
    scores_kernel<<<dim3(16, 16, 32), 256, SC_SMEM_BYTES>>>(q, k, wbuf, stats);

    // 3) rescale to final weights (in place) + PV (pipelined)
    softmax_pv<<<dim3(1, 16, 32), 256, SPV_SMEM_BYTES>>>(v, wbuf, stats, attn);

    // 4) out = attn @ Wo^T
    proj_nt<<<dim3(8, 32, 1), 256>>>(attn, Wo, out, attn, Wo, out, attn, Wo, out);
}

// round 9
// speedup vs baseline: 1.3778x; 1.0007x over previous
#include <cuda_runtime.h>
#include <cstdint>

// Problem constants
static constexpr int  Bc  = 2;
static constexpr int  Tc  = 2048;
static constexpr int  Dc  = 1024;
static constexpr int  Hc  = 16;
static constexpr long long OUT_ELEMS = (long long)Bc * Tc * Dc;          // 4194304
static constexpr long long W_ELEMS   = (long long)Bc * Hc * Tc * Tc;     // 134217728

// Scratch (allocation-free rule: __device__ globals)
__device__ float g_q[Bc * Tc * Dc];
__device__ float g_k[Bc * Tc * Dc];
__device__ float g_v[Bc * Tc * Dc];
__device__ float g_attn[Bc * Tc * Dc];
__device__ float g_stats[(size_t)Bc * Hc * Tc * 16 * 2];                 // (m,l) per row per col-tile
__device__ float g_weights[(size_t)Bc * Hc * Tc * Tc];  // fallback if out_size lacks weights

// ---------------------------------------------------------------------------
__device__ __forceinline__ uint32_t f2tf(float x) {
    uint32_t r;
    asm("cvt.rna.tf32.f32 %0, %1;" : "=r"(r) : "f"(x));
    return r;
}

__device__ __forceinline__ void mma_tf32(float* c, const uint32_t* a, const uint32_t* b) {
    asm volatile(
        "mma.sync.aligned.m16n8k8.row.col.f32.tf32.tf32.f32 "
        "{%0,%1,%2,%3}, {%4,%5,%6,%7}, {%8,%9}, {%0,%1,%2,%3};\n"
        : "+f"(c[0]), "+f"(c[1]), "+f"(c[2]), "+f"(c[3])
        : "r"(a[0]), "r"(a[1]), "r"(a[2]), "r"(a[3]), "r"(b[0]), "r"(b[1]));
}

// ---------------------------------------------------------------------------
// Projection GEMM-NT (software-pipelined): C = A @ W^T, 4096x1024x1024.
// Iter k0: stash prefetched regs -> smem (f2tf at store, paired layouts),
// sync, prefetch k0+32 (LDGs overlap MMA), MMA 4 kc, sync.
// grid (8, 32, z); z selects one of 3 independent (A,W,C) triples.
// ---------------------------------------------------------------------------
__global__ __launch_bounds__(256, 2) void proj_nt(
    const float* __restrict__ A0, const float* __restrict__ W0, float* __restrict__ C0,
    const float* __restrict__ A1, const float* __restrict__ W1, float* __restrict__ C1,
    const float* __restrict__ A2, const float* __restrict__ W2, float* __restrict__ C2)
{
    __shared__ uint32_t As2[64 * 72];
    __shared__ uint32_t Bs2[128 * 40];

    const int z = blockIdx.z;
    const float* A = z == 0 ? A0 : (z == 1 ? A1 : A2);
    const float* W = z == 0 ? W0 : (z == 1 ? W1 : W2);
    float*       C = z == 0 ? C0 : (z == 1 ? C1 : C2);

    const float* Ab = A + (long long)blockIdx.y * 128 * 1024;
    const float* Wb = W + (long long)blockIdx.x * 128 * 1024;
    float*       Cb = C + (long long)blockIdx.y * 128 * 1024 + blockIdx.x * 128;

    const int t = threadIdx.x, warp = t >> 5, lane = t & 31;
    const int g = lane >> 2, tg = lane & 3;
    const int m_half = (warp & 1);
    const int n_base = (warp >> 1) * 32;

    // fixed per-thread load coordinates
    int prA[2], rA[2], nB[2];
    prA[0] = t >> 3;       prA[1] = 32 + (t >> 3);
    rA[0] = (prA[0] >> 3) * 16 + (prA[0] & 7);
    rA[1] = (prA[1] >> 3) * 16 + (prA[1] & 7);
    const int c4 = (t & 7) * 4;
    nB[0] = t >> 2;        nB[1] = 64 + (t >> 2);
    const int c8 = (t & 3) * 8;

    float acc[4][4][4];
#pragma unroll
    for (int i = 0; i < 4; i++)
#pragma unroll
        for (int j = 0; j < 4; j++)
#pragma unroll
            for (int r = 0; r < 4; r++) acc[i][j][r] = 0.f;

    float4 pa_lo[2], pa_hi[2], pw_lo[2], pw_hi[2];
    // prefetch k0 = 0
#pragma unroll
    for (int i = 0; i < 2; i++) {
        const float* s0 = Ab + (long long)rA[i] * 1024 + c4;
        pa_lo[i] = *(const float4*)s0;
        pa_hi[i] = *(const float4*)(s0 + 8 * 1024);
        const float* w0 = Wb + (long long)nB[i] * 1024 + c8;
        pw_lo[i] = *(const float4*)w0;
        pw_hi[i] = *(const float4*)(w0 + 4);
    }

    for (int k0 = 0; k0 < 1024; k0 += 32) {
        // ---- stash phase: regs -> smem (f2tf at store)
#pragma unroll
        for (int i = 0; i < 2; i++) {
            uint32_t* d = &As2[prA[i] * 72 + c4 * 2];
            ((uint2*)d)[0] = make_uint2(f2tf(pa_lo[i].x), f2tf(pa_hi[i].x));
            ((uint2*)d)[1] = make_uint2(f2tf(pa_lo[i].y), f2tf(pa_hi[i].y));
            ((uint2*)d)[2] = make_uint2(f2tf(pa_lo[i].z), f2tf(pa_hi[i].z));
            ((uint2*)d)[3] = make_uint2(f2tf(pa_lo[i].w), f2tf(pa_hi[i].w));
            uint32_t* e = &Bs2[nB[i] * 40 + c8];
            ((uint2*)e)[0] = make_uint2(f2tf(pw_lo[i].x), f2tf(pw_hi[i].x));
            ((uint2*)e)[1] = make_uint2(f2tf(pw_lo[i].y), f2tf(pw_hi[i].y));
            ((uint2*)e)[2] = make_uint2(f2tf(pw_lo[i].z), f2tf(pw_hi[i].z));
            ((uint2*)e)[3] = make_uint2(f2tf(pw_lo[i].w), f2tf(pw_hi[i].w));
        }
        __syncthreads();

        // ---- prefetch next iter (overlaps MMA)
        if (k0 < 992) {
            const int kn = k0 + 32;
#pragma unroll
            for (int i = 0; i < 2; i++) {
                const float* s0 = Ab + (long long)rA[i] * 1024 + kn + c4;
                pa_lo[i] = *(const float4*)s0;
                pa_hi[i] = *(const float4*)(s0 + 8 * 1024);
                const float* w0 = Wb + (long long)nB[i] * 1024 + kn + c8;
                pw_lo[i] = *(const float4*)w0;
                pw_hi[i] = *(const float4*)(w0 + 4);
            }
        }

        // ---- MMA
#pragma unroll
        for (int kc = 0; kc < 4; kc++) {
            uint32_t af[4][4];
#pragma unroll
            for (int mi = 0; mi < 4; mi++) {
                const int rowp = (m_half * 4 + mi) * 8 + g;
                uint2 qa = *(const uint2*)&As2[rowp * 72 + (kc * 8 + tg) * 2];
                uint2 qb = *(const uint2*)&As2[rowp * 72 + (kc * 8 + 4 + tg) * 2];
                af[mi][0] = qa.x; af[mi][1] = qa.y; af[mi][2] = qb.x; af[mi][3] = qb.y;
            }
#pragma unroll
            for (int ni = 0; ni < 4; ni++) {
                uint2 bb = *(const uint2*)&Bs2[(n_base + ni * 8 + g) * 40 + kc * 8 + tg * 2];
#pragma unroll
                for (int mi = 0; mi < 4; mi++)
                    mma_tf32(acc[mi][ni], af[mi], &bb.x);
            }
        }
        __syncthreads();
    }

#pragma unroll
    for (int mi = 0; mi < 4; mi++) {
#pragma unroll
        for (int ni = 0; ni < 4; ni++) {
            const int row = m_half * 64 + mi * 16 + g;
            const int col = n_base + ni * 8 + tg * 2;
            *(float2*)(Cb + (long long)row * 1024 + col) =
                make_float2(acc[mi][ni][0], acc[mi][ni][1]);
            *(float2*)(Cb + (long long)(row + 8) * 1024 + col) =
                make_float2(acc[mi][ni][2], acc[mi][ni][3]);
        }
    }
}

// ---------------------------------------------------------------------------
// Scores: one CTA = 128x128 tile of S = (Q K^T)/8 for one (b,h).
// Separate Q/K smem, per-kc fragment loads, e-store epilogue:
// per-tile row max m, e = exp(s-m) kept in regs, row sum l; stores e + (m,l).
// ---------------------------------------------------------------------------
static constexpr int SC_SMEM_BYTES = (17408 + 512 + 128 + 512) * 4;   // 74240 B

__global__ __launch_bounds__(256, 2) void scores_kernel(
    const float* __restrict__ q, const float* __restrict__ k,
    float* __restrict__ eout, float* __restrict__ stats)
{
    extern __shared__ uint32_t sm[];
    uint32_t* Qs  = sm;                        // [128][68]
    uint32_t* Ks  = sm + 8704;                 // [128][68]
    float*    wred = (float*)(sm + 17408);     // [128][4]
    float*    mrow = (float*)(sm + 17920);     // [128]
    float*    wsum = (float*)(sm + 18048);     // [128][4]

    const int bh = blockIdx.z;
    const int b = bh >> 4, h = bh & 15;
    const int qbase = blockIdx.y * 128;
    const int nbase = blockIdx.x * 128;
    const int t = threadIdx.x, warp = t >> 5, lane = t & 31;
    const int g = lane >> 2, tg = lane & 3;
    const int m_half = warp & 1;
    const int n_off  = (warp >> 1) * 32;
    const int nwarp  = warp >> 1;

    const float* qp = q + ((long long)(b * Tc + qbase)) * Dc + h * 64;
    const float* kp = k + ((long long)(b * Tc + nbase)) * Dc + h * 64;

    // load Q and K tiles (interleaved -> high MLP)
#pragma unroll
    for (int i = 0; i < 8; i++) {
        const int idx = i * 256 + t;
        const int r = idx >> 4, c4 = (idx & 15) * 4;
        float4 xq = *(const float4*)(qp + (long long)r * Dc + c4);
        float4 xk = *(const float4*)(kp + (long long)r * Dc + c4);
        uint32_t* dq = &Qs[r * 68 + c4];
        dq[0] = f2tf(xq.x); dq[1] = f2tf(xq.y); dq[2] = f2tf(xq.z); dq[3] = f2tf(xq.w);
        uint32_t* dk = &Ks[r * 68 + c4];
        dk[0] = f2tf(xk.x); dk[1] = f2tf(xk.y); dk[2] = f2tf(xk.z); dk[3] = f2tf(xk.w);
    }
    __syncthreads();

    float sacc[4][4][4];
#pragma unroll
    for (int i = 0; i < 4; i++)
#pragma unroll
        for (int j = 0; j < 4; j++)
#pragma unroll
            for (int r = 0; r < 4; r++) sacc[i][j][r] = 0.f;

#pragma unroll
    for (int kc = 0; kc < 8; kc++) {
        uint32_t af[4][4], bf[4][2];
#pragma unroll
        for (int mi = 0; mi < 4; mi++) {
            const int r0 = (m_half * 64 + mi * 16 + g) * 68;
            af[mi][0] = Qs[r0 + kc * 8 + tg];
            af[mi][1] = Qs[r0 + 8 * 68 + kc * 8 + tg];
            af[mi][2] = Qs[r0 + kc * 8 + 4 + tg];
            af[mi][3] = Qs[r0 + 8 * 68 + kc * 8 + 4 + tg];
        }
#pragma unroll
        for (int ni = 0; ni < 4; ni++) {
            const int n0 = (n_off + ni * 8 + g) * 68;
            bf[ni][0] = Ks[n0 + kc * 8 + tg];
            bf[ni][1] = Ks[n0 + kc * 8 + 4 + tg];
        }
#pragma unroll
        for (int mi = 0; mi < 4; mi++)
#pragma unroll
            for (int ni = 0; ni < 4; ni++)
                mma_tf32(sacc[mi][ni], af[mi], bf[ni]);
    }

    // scale
#pragma unroll
    for (int mi = 0; mi < 4; mi++)
#pragma unroll
        for (int ni = 0; ni < 4; ni++)
#pragma unroll
            for (int r = 0; r < 4; r++) sacc[mi][ni][r] *= 0.125f;

    // per-tile row max
#pragma unroll
    for (int mi = 0; mi < 4; mi++) {
        float v0 = -1e30f, v1 = -1e30f;
#pragma unroll
        for (int ni = 0; ni < 4; ni++) {
            v0 = fmaxf(v0, fmaxf(sacc[mi][ni][0], sacc[mi][ni][1]));
            v1 = fmaxf(v1, fmaxf(sacc[mi][ni][2], sacc[mi][ni][3]));
        }
        v0 = fmaxf(v0, __shfl_xor_sync(0xffffffffu, v0, 1));
        v0 = fmaxf(v0, __shfl_xor_sync(0xffffffffu, v0, 2));
        v1 = fmaxf(v1, __shfl_xor_sync(0xffffffffu, v1, 1));
        v1 = fmaxf(v1, __shfl_xor_sync(0xffffffffu, v1, 2));
        if (tg == 0) {
            wred[(m_half * 64 + mi * 16 + g) * 4 + nwarp]     = v0;
            wred[(m_half * 64 + mi * 16 + 8 + g) * 4 + nwarp] = v1;
        }
    }
    __syncthreads();
    if (t < 128) {
        mrow[t] = fmaxf(fmaxf(wred[t * 4], wred[t * 4 + 1]),
                        fmaxf(wred[t * 4 + 2], wred[t * 4 + 3]));
    }
    __syncthreads();

    // e = exp(s - m) (kept in sacc), row sum
#pragma unroll
    for (int mi = 0; mi < 4; mi++) {
        const float m0 = mrow[m_half * 64 + mi * 16 + g];
        const float m1 = mrow[m_half * 64 + mi * 16 + 8 + g];
        float s0 = 0.f, s1 = 0.f;
#pragma unroll
        for (int ni = 0; ni < 4; ni++) {
            sacc[mi][ni][0] = __expf(sacc[mi][ni][0] - m0);
            sacc[mi][ni][1] = __expf(sacc[mi][ni][1] - m0);
            sacc[mi][ni][2] = __expf(sacc[mi][ni][2] - m1);
            sacc[mi][ni][3] = __expf(sacc[mi][ni][3] - m1);
            s0 += sacc[mi][ni][0] + sacc[mi][ni][1];
            s1 += sacc[mi][ni][2] + sacc[mi][ni][3];
        }
        s0 += __shfl_xor_sync(0xffffffffu, s0, 1);
        s0 += __shfl_xor_sync(0xffffffffu, s0, 2);
        s1 += __shfl_xor_sync(0xffffffffu, s1, 1);
        s1 += __shfl_xor_sync(0xffffffffu, s1, 2);
        if (tg == 0) {
            wsum[(m_half * 64 + mi * 16 + g) * 4 + nwarp]     = s0;
            wsum[(m_half * 64 + mi * 16 + 8 + g) * 4 + nwarp] = s1;
        }
    }
    __syncthreads();
    if (t < 128) {
        float l = wsum[t * 4] + wsum[t * 4 + 1] + wsum[t * 4 + 2] + wsum[t * 4 + 3];
        float2* st = (float2*)(stats + (((long long)bh * Tc + qbase + t) * 16 + blockIdx.x) * 2);
        *st = make_float2(mrow[t], l);
    }

    // store e tile
#pragma unroll
    for (int mi = 0; mi < 4; mi++) {
#pragma unroll
        for (int ni = 0; ni < 4; ni++) {
            const int row = m_half * 64 + mi * 16 + g;
            const int col = nbase + n_off + ni * 8 + tg * 2;
            float* w0 = eout + ((long long)bh * Tc + qbase + row) * Tc + col;
            *(float2*)w0 = make_float2(sacc[mi][ni][0], sacc[mi][ni][1]);
            *(float2*)(w0 + 8 * Tc) = make_float2(sacc[mi][ni][2], sacc[mi][ni][3]);
        }
    }
}

// ---------------------------------------------------------------------------
// softmax+PV (software-pipelined): one CTA = 128 query rows of one (b,h).
// Iter sub: stash prefetched regs to smem (w STG + tf32 P/V STS), sync,
// prefetch sub+1 (LDGs overlap MMA), MMA, sync.  Exp-free stream loop.
// smem (words): Pp[128*68] @0, Vs[64*72] @8704, rsc[128*16] @13312
// ---------------------------------------------------------------------------
static constexpr int SPV_SMEM_BYTES = (8704 + 4608 + 2048) * 4;   // 61440 B

__global__ __launch_bounds__(256, 2) void softmax_pv(
    const float* __restrict__ v, float* __restrict__ w,
    const float* __restrict__ stats, float* __restrict__ attn)
{
    extern __shared__ uint32_t sm[];
    uint32_t* Pp = sm;
    uint32_t* Vs = sm + 8704;
    float*    rsc = (float*)(sm + 13312);     // [128][16]

    const int bh = blockIdx.z;
    const int b = bh >> 4, h = bh & 15;
    const int qbase = blockIdx.y * 128;
    const int t = threadIdx.x, warp = t >> 5, lane = t & 31;
    const int g = lane >> 2, tg = lane & 3;

    const float* vp = v + ((long long)b * Tc) * Dc + h * 64;
    float* wb = w + ((long long)bh * Tc + qbase) * Tc;

    // per-row final stats -> 16 per-tile rescale factors
    if (t < 128) {
        const float2* st = (const float2*)(stats + (((long long)bh * Tc + qbase + t) * 16) * 2);
        float2 sl[16];
        float m = -1e30f;
#pragma unroll
        for (int j = 0; j < 16; j++) { sl[j] = st[j]; m = fmaxf(m, sl[j].x); }
        float l = 0.f;
#pragma unroll
        for (int j = 0; j < 16; j++) l += sl[j].y * __expf(sl[j].x - m);
        const float inv = 1.0f / l;
#pragma unroll
        for (int j = 0; j < 16; j++) rsc[t * 16 + j] = __expf(sl[j].x - m) * inv;
    }

    // per-thread fixed addressing for the streamed strips
    const int erow = t >> 4;                  // 0..15 (x8 strips of 16 rows)
    const int ec4  = (t & 15) * 4;
    const int vrow = t >> 4;                  // 0..15 (x4 strips of 16 rows)
    const int vc4  = (t & 15) * 4;

    float4 pe[8], pv4[4];
    // prefetch sub = 0
#pragma unroll
    for (int i = 0; i < 4; i++)
        pv4[i] = *(const float4*)(vp + (long long)(i * 16 + vrow) * Dc + vc4);
#pragma unroll
    for (int i = 0; i < 8; i++)
        pe[i] = *(const float4*)(wb + (long long)(i * 16 + erow) * Tc + ec4);

    __syncthreads();   // rsc ready

    float oacc[8][4];
#pragma unroll
    for (int nf = 0; nf < 8; nf++)
#pragma unroll
        for (int r = 0; r < 4; r++) oacc[nf][r] = 0.f;

    for (int sub = 0; sub < 32; sub++) {
        const int j = sub >> 1;
        // ---- stash phase: V tf32 -> smem, e -> normalized w (STG) + tf32 P -> smem
#pragma unroll
        for (int i = 0; i < 4; i++) {
            uint32_t* d = &Vs[(i * 16 + vrow) * 72 + vc4];
            d[0] = f2tf(pv4[i].x); d[1] = f2tf(pv4[i].y);
            d[2] = f2tf(pv4[i].z); d[3] = f2tf(pv4[i].w);
        }
#pragma unroll
        for (int i = 0; i < 8; i++) {
            const int row = i * 16 + erow;
            const float sc = rsc[row * 16 + j];
            float4 p = make_float4(pe[i].x * sc, pe[i].y * sc, pe[i].z * sc, pe[i].w * sc);
            *(float4*)(wb + (long long)row * Tc + sub * 64 + ec4) = p;
            uint32_t* d = &Pp[row * 68 + ec4];
            d[0] = f2tf(p.x); d[1] = f2tf(p.y); d[2] = f2tf(p.z); d[3] = f2tf(p.w);
        }
        __syncthreads();

        // ---- prefetch sub+1 (LDGs overlap the MMA below)
        if (sub < 31) {
            const float* vpn = vp + (long long)(sub + 1) * 64 * Dc;
            const float* wbn = wb + (sub + 1) * 64;
#pragma unroll
            for (int i = 0; i < 4; i++)
                pv4[i] = *(const float4*)(vpn + (long long)(i * 16 + vrow) * Dc + vc4);
#pragma unroll
            for (int i = 0; i < 8; i++)
                pe[i] = *(const float4*)(wbn + (long long)(i * 16 + erow) * Tc + ec4);
        }

        // ---- O += P @ V
#pragma unroll
        for (int kc = 0; kc < 8; kc++) {
            const int r0 = (warp * 16 + g) * 68;
            uint32_t a[4];
            a[0] = Pp[r0 + kc * 8 + tg];
            a[1] = Pp[r0 + 8 * 68 + kc * 8 + tg];
            a[2] = Pp[r0 + kc * 8 + 4 + tg];
            a[3] = Pp[r0 + 8 * 68 + kc * 8 + 4 + tg];
#pragma unroll
            for (int nf = 0; nf < 8; nf++) {
                uint32_t bfr[2];
                bfr[0] = Vs[(kc * 8 + tg) * 72 + nf * 8 + g];
                bfr[1] = Vs[(kc * 8 + 4 + tg) * 72 + nf * 8 + g];
                mma_tf32(oacc[nf], a, bfr);
            }
        }
        __syncthreads();
    }

    // write O into attn buffer [B,T,D]
    float* op0 = attn + ((long long)(b * Tc + qbase + warp * 16 + g)) * Dc + h * 64;
    float* op1 = op0 + 8 * Dc;
#pragma unroll
    for (int nf = 0; nf < 8; nf++) {
        const int c = nf * 8 + tg * 2;
        *(float2*)(op0 + c) = make_float2(oacc[nf][0], oacc[nf][1]);
        *(float2*)(op1 + c) = make_float2(oacc[nf][2], oacc[nf][3]);
    }
}

// ---------------------------------------------------------------------------
extern "C" void kernel_launch(void* const* d_in, const int* /*in_sizes*/, int /*n_in*/,
                              void* d_out, int out_size)
{
    const float* query = (const float*)d_in[0];
    const float* key_i = (const float*)d_in[1];
    const float* value = (const float*)d_in[2];
    const float* Wq    = (const float*)d_in[3];
    const float* Wk    = (const float*)d_in[4];
    const float* Wv    = (const float*)d_in[5];
    const float* Wo    = (const float*)d_in[6];
    float* out = (float*)d_out;

    float *q, *k, *v, *attn, *stats, *wbuf;
    cudaGetSymbolAddress((void**)&q,     g_q);
    cudaGetSymbolAddress((void**)&k,     g_k);
    cudaGetSymbolAddress((void**)&v,     g_v);
    cudaGetSymbolAddress((void**)&attn,  g_attn);
    cudaGetSymbolAddress((void**)&stats, g_stats);
    if ((long long)out_size >= OUT_ELEMS + W_ELEMS) {
        wbuf = out + OUT_ELEMS;                 // tuple-concat output: [out | weights]
    } else {
        cudaGetSymbolAddress((void**)&wbuf, g_weights);
    }

    cudaFuncSetAttribute(scores_kernel, cudaFuncAttributeMaxDynamicSharedMemorySize,
                         SC_SMEM_BYTES);
    cudaFuncSetAttribute(softmax_pv, cudaFuncAttributeMaxDynamicSharedMemorySize,
                         SPV_SMEM_BYTES);

    // 1) Q/K/V projections in one launch (pipelined)
    proj_nt<<<dim3(8, 32, 3), 256>>>(query, Wq, q, key_i, Wk, k, value, Wv, v);

    // 2) e = exp(s - m_tile) + per-tile stats
    scores_kernel<<<dim3(16, 16, 32), 256, SC_SMEM_BYTES>>>(q, k, wbuf, stats);

    // 3) rescale to final weights (in place) + PV (pipelined)
    softmax_pv<<<dim3(1, 16, 32), 256, SPV_SMEM_BYTES>>>(v, wbuf, stats, attn);

    // 4) out = attn @ Wo^T (pipelined)
    proj_nt<<<dim3(8, 32, 1), 256>>>(attn, Wo, out, attn, Wo, out, attn, Wo, out);
}

// round 10
// speedup vs baseline: 1.4568x; 1.0574x over previous
#include <cuda_runtime.h>
#include <cstdint>

// Problem constants
static constexpr int  Bc  = 2;
static constexpr int  Tc  = 2048;
static constexpr int  Dc  = 1024;
static constexpr int  Hc  = 16;
static constexpr long long OUT_ELEMS = (long long)Bc * Tc * Dc;          // 4194304
static constexpr long long W_ELEMS   = (long long)Bc * Hc * Tc * Tc;     // 134217728

// Scratch (allocation-free rule: __device__ globals)
__device__ float g_q[Bc * Tc * Dc];
__device__ float g_k[Bc * Tc * Dc];
__device__ float g_v[Bc * Tc * Dc];
__device__ float g_attn[Bc * Tc * Dc];
__device__ float g_stats[(size_t)Bc * Hc * Tc * 16 * 2];                 // (m,l) per row per col-tile
__device__ float g_weights[(size_t)Bc * Hc * Tc * Tc];  // fallback if out_size lacks weights

// ---------------------------------------------------------------------------
__device__ __forceinline__ uint32_t f2tf(float x) {
    uint32_t r;
    asm("cvt.rna.tf32.f32 %0, %1;" : "=r"(r) : "f"(x));
    return r;
}

__device__ __forceinline__ void mma_tf32(float* c, const uint32_t* a, const uint32_t* b) {
    asm volatile(
        "mma.sync.aligned.m16n8k8.row.col.f32.tf32.tf32.f32 "
        "{%0,%1,%2,%3}, {%4,%5,%6,%7}, {%8,%9}, {%0,%1,%2,%3};\n"
        : "+f"(c[0]), "+f"(c[1]), "+f"(c[2]), "+f"(c[3])
        : "r"(a[0]), "r"(a[1]), "r"(a[2]), "r"(a[3]), "r"(b[0]), "r"(b[1]));
}

// ---------------------------------------------------------------------------
// Projection GEMM-NT, double-buffered: C = A @ W^T, 4096x1024x1024.
// Per iter: prefetch LDGs (k0+32) -> MMA on buf[cur] -> stash to buf[cur^1]
// -> ONE sync.  Dynamic smem: 2 x (As2 64*72 + Bs2 128*40) words = 77824 B.
// grid (8, 32, z); z selects one of 3 independent (A,W,C) triples.
// ---------------------------------------------------------------------------
static constexpr int PROJ_BUF_WORDS = 64 * 72 + 128 * 40;   // 9728
static constexpr int PROJ_SMEM_BYTES = 2 * PROJ_BUF_WORDS * 4;  // 77824

__global__ __launch_bounds__(256, 2) void proj_nt(
    const float* __restrict__ A0, const float* __restrict__ W0, float* __restrict__ C0,
    const float* __restrict__ A1, const float* __restrict__ W1, float* __restrict__ C1,
    const float* __restrict__ A2, const float* __restrict__ W2, float* __restrict__ C2)
{
    extern __shared__ uint32_t dsm[];

    const int z = blockIdx.z;
    const float* A = z == 0 ? A0 : (z == 1 ? A1 : A2);
    const float* W = z == 0 ? W0 : (z == 1 ? W1 : W2);
    float*       C = z == 0 ? C0 : (z == 1 ? C1 : C2);

    const float* Ab = A + (long long)blockIdx.y * 128 * 1024;
    const float* Wb = W + (long long)blockIdx.x * 128 * 1024;
    float*       Cb = C + (long long)blockIdx.y * 128 * 1024 + blockIdx.x * 128;

    const int t = threadIdx.x, warp = t >> 5, lane = t & 31;
    const int g = lane >> 2, tg = lane & 3;
    const int m_half = (warp & 1);
    const int n_base = (warp >> 1) * 32;

    // fixed per-thread load coordinates
    int prA[2], rA[2], nB[2];
    prA[0] = t >> 3;       prA[1] = 32 + (t >> 3);
    rA[0] = (prA[0] >> 3) * 16 + (prA[0] & 7);
    rA[1] = (prA[1] >> 3) * 16 + (prA[1] & 7);
    const int c4 = (t & 7) * 4;
    nB[0] = t >> 2;        nB[1] = 64 + (t >> 2);
    const int c8 = (t & 3) * 8;

    float acc[4][4][4];
#pragma unroll
    for (int i = 0; i < 4; i++)
#pragma unroll
        for (int j = 0; j < 4; j++)
#pragma unroll
            for (int r = 0; r < 4; r++) acc[i][j][r] = 0.f;

    float4 pa_lo[2], pa_hi[2], pw_lo[2], pw_hi[2];
    // prefetch k0 = 0
#pragma unroll
    for (int i = 0; i < 2; i++) {
        const float* s0 = Ab + (long long)rA[i] * 1024 + c4;
        pa_lo[i] = *(const float4*)s0;
        pa_hi[i] = *(const float4*)(s0 + 8 * 1024);
        const float* w0 = Wb + (long long)nB[i] * 1024 + c8;
        pw_lo[i] = *(const float4*)w0;
        pw_hi[i] = *(const float4*)(w0 + 4);
    }

    // stash k0=0 into buffer 0
    {
        uint32_t* As2 = dsm;
        uint32_t* Bs2 = dsm + 64 * 72;
#pragma unroll
        for (int i = 0; i < 2; i++) {
            uint32_t* d = &As2[prA[i] * 72 + c4 * 2];
            ((uint2*)d)[0] = make_uint2(f2tf(pa_lo[i].x), f2tf(pa_hi[i].x));
            ((uint2*)d)[1] = make_uint2(f2tf(pa_lo[i].y), f2tf(pa_hi[i].y));
            ((uint2*)d)[2] = make_uint2(f2tf(pa_lo[i].z), f2tf(pa_hi[i].z));
            ((uint2*)d)[3] = make_uint2(f2tf(pa_lo[i].w), f2tf(pa_hi[i].w));
            uint32_t* e = &Bs2[nB[i] * 40 + c8];
            ((uint2*)e)[0] = make_uint2(f2tf(pw_lo[i].x), f2tf(pw_hi[i].x));
            ((uint2*)e)[1] = make_uint2(f2tf(pw_lo[i].y), f2tf(pw_hi[i].y));
            ((uint2*)e)[2] = make_uint2(f2tf(pw_lo[i].z), f2tf(pw_hi[i].z));
            ((uint2*)e)[3] = make_uint2(f2tf(pw_lo[i].w), f2tf(pw_hi[i].w));
        }
    }
    __syncthreads();

    for (int k0 = 0; k0 < 1024; k0 += 32) {
        const int cur = (k0 >> 5) & 1;
        uint32_t* Acur = dsm + cur * PROJ_BUF_WORDS;
        uint32_t* Bcur = Acur + 64 * 72;
        uint32_t* Anx  = dsm + (cur ^ 1) * PROJ_BUF_WORDS;
        uint32_t* Bnx  = Anx + 64 * 72;
        const bool more = (k0 < 992);

        // ---- prefetch next iter (LDGs retire under the MMA below)
        if (more) {
            const int kn = k0 + 32;
#pragma unroll
            for (int i = 0; i < 2; i++) {
                const float* s0 = Ab + (long long)rA[i] * 1024 + kn + c4;
                pa_lo[i] = *(const float4*)s0;
                pa_hi[i] = *(const float4*)(s0 + 8 * 1024);
                const float* w0 = Wb + (long long)nB[i] * 1024 + kn + c8;
                pw_lo[i] = *(const float4*)w0;
                pw_hi[i] = *(const float4*)(w0 + 4);
            }
        }

        // ---- MMA on current buffer
#pragma unroll
        for (int kc = 0; kc < 4; kc++) {
            uint32_t af[4][4];
#pragma unroll
            for (int mi = 0; mi < 4; mi++) {
                const int rowp = (m_half * 4 + mi) * 8 + g;
                uint2 qa = *(const uint2*)&Acur[rowp * 72 + (kc * 8 + tg) * 2];
                uint2 qb = *(const uint2*)&Acur[rowp * 72 + (kc * 8 + 4 + tg) * 2];
                af[mi][0] = qa.x; af[mi][1] = qa.y; af[mi][2] = qb.x; af[mi][3] = qb.y;
            }
#pragma unroll
            for (int ni = 0; ni < 4; ni++) {
                uint2 bb = *(const uint2*)&Bcur[(n_base + ni * 8 + g) * 40 + kc * 8 + tg * 2];
#pragma unroll
                for (int mi = 0; mi < 4; mi++)
                    mma_tf32(acc[mi][ni], af[mi], &bb.x);
            }
        }

        // ---- stash prefetched regs into the other buffer
        if (more) {
#pragma unroll
            for (int i = 0; i < 2; i++) {
                uint32_t* d = &Anx[prA[i] * 72 + c4 * 2];
                ((uint2*)d)[0] = make_uint2(f2tf(pa_lo[i].x), f2tf(pa_hi[i].x));
                ((uint2*)d)[1] = make_uint2(f2tf(pa_lo[i].y), f2tf(pa_hi[i].y));
                ((uint2*)d)[2] = make_uint2(f2tf(pa_lo[i].z), f2tf(pa_hi[i].z));
                ((uint2*)d)[3] = make_uint2(f2tf(pa_lo[i].w), f2tf(pa_hi[i].w));
                uint32_t* e = &Bnx[nB[i] * 40 + c8];
                ((uint2*)e)[0] = make_uint2(f2tf(pw_lo[i].x), f2tf(pw_hi[i].x));
                ((uint2*)e)[1] = make_uint2(f2tf(pw_lo[i].y), f2tf(pw_hi[i].y));
                ((uint2*)e)[2] = make_uint2(f2tf(pw_lo[i].z), f2tf(pw_hi[i].z));
                ((uint2*)e)[3] = make_uint2(f2tf(pw_lo[i].w), f2tf(pw_hi[i].w));
            }
        }
        __syncthreads();
    }

#pragma unroll
    for (int mi = 0; mi < 4; mi++) {
#pragma unroll
        for (int ni = 0; ni < 4; ni++) {
            const int row = m_half * 64 + mi * 16 + g;
            const int col = n_base + ni * 8 + tg * 2;
            *(float2*)(Cb + (long long)row * 1024 + col) =
                make_float2(acc[mi][ni][0], acc[mi][ni][1]);
            *(float2*)(Cb + (long long)(row + 8) * 1024 + col) =
                make_float2(acc[mi][ni][2], acc[mi][ni][3]);
        }
    }
}

// ---------------------------------------------------------------------------
// Scores (split-K pipelined): one CTA = 128x128 tile of S = (Q K^T)/8.
// Load Q full + K cols 0-31 to smem, prefetch K cols 32-63 into regs,
// sync, MMA kc0-3 (prefetch LDGs retire underneath), stash K-hi, sync,
// MMA kc4-7.  e-store epilogue unchanged.
// ---------------------------------------------------------------------------
static constexpr int SC_SMEM_BYTES = (17408 + 512 + 128 + 512) * 4;   // 74240 B

__global__ __launch_bounds__(256, 2) void scores_kernel(
    const float* __restrict__ q, const float* __restrict__ k,
    float* __restrict__ eout, float* __restrict__ stats)
{
    extern __shared__ uint32_t sm[];
    uint32_t* Qs  = sm;                        // [128][68]
    uint32_t* Ks  = sm + 8704;                 // [128][68]
    float*    wred = (float*)(sm + 17408);     // [128][4]
    float*    mrow = (float*)(sm + 17920);     // [128]
    float*    wsum = (float*)(sm + 18048);     // [128][4]

    const int bh = blockIdx.z;
    const int b = bh >> 4, h = bh & 15;
    const int qbase = blockIdx.y * 128;
    const int nbase = blockIdx.x * 128;
    const int t = threadIdx.x, warp = t >> 5, lane = t & 31;
    const int g = lane >> 2, tg = lane & 3;
    const int m_half = warp & 1;
    const int n_off  = (warp >> 1) * 32;
    const int nwarp  = warp >> 1;

    const float* qp = q + ((long long)(b * Tc + qbase)) * Dc + h * 64;
    const float* kp = k + ((long long)(b * Tc + nbase)) * Dc + h * 64;

    // ---- load Q full + K cols 0-31; prefetch K cols 32-63 into regs
#pragma unroll
    for (int i = 0; i < 8; i++) {
        const int idx = i * 256 + t;
        const int r = idx >> 4, c4 = (idx & 15) * 4;
        float4 xq = *(const float4*)(qp + (long long)r * Dc + c4);
        uint32_t* dq = &Qs[r * 68 + c4];
        dq[0] = f2tf(xq.x); dq[1] = f2tf(xq.y); dq[2] = f2tf(xq.z); dq[3] = f2tf(xq.w);
    }
    const int kr = t >> 1;                 // 0..127 (2 col-chunks per row half)
    const int kc4 = (t & 1) * 4;           // covers cols 0..7 per i-step of 8
    float4 pk[4];
#pragma unroll
    for (int i = 0; i < 4; i++) {
        const int idx = i * 256 + t;
        const int r = idx >> 3, c4 = (idx & 7) * 4;       // cols 0..28
        float4 xk = *(const float4*)(kp + (long long)r * Dc + c4);
        uint32_t* dk = &Ks[r * 68 + c4];
        dk[0] = f2tf(xk.x); dk[1] = f2tf(xk.y); dk[2] = f2tf(xk.z); dk[3] = f2tf(xk.w);
    }
#pragma unroll
    for (int i = 0; i < 4; i++) {
        const int idx = i * 256 + t;
        const int r = idx >> 3, c4 = 32 + (idx & 7) * 4;  // cols 32..60
        pk[i] = *(const float4*)(kp + (long long)r * Dc + c4);
    }
    __syncthreads();

    float sacc[4][4][4];
#pragma unroll
    for (int i = 0; i < 4; i++)
#pragma unroll
        for (int j = 0; j < 4; j++)
#pragma unroll
            for (int r = 0; r < 4; r++) sacc[i][j][r] = 0.f;

    // ---- MMA on K-lo (kc 0-3); prefetch LDGs for K-hi retire underneath
#pragma unroll
    for (int kc = 0; kc < 4; kc++) {
        uint32_t af[4][4], bf[4][2];
#pragma unroll
        for (int mi = 0; mi < 4; mi++) {
            const int r0 = (m_half * 64 + mi * 16 + g) * 68;
            af[mi][0] = Qs[r0 + kc * 8 + tg];
            af[mi][1] = Qs[r0 + 8 * 68 + kc * 8 + tg];
            af[mi][2] = Qs[r0 + kc * 8 + 4 + tg];
            af[mi][3] = Qs[r0 + 8 * 68 + kc * 8 + 4 + tg];
        }
#pragma unroll
        for (int ni = 0; ni < 4; ni++) {
            const int n0 = (n_off + ni * 8 + g) * 68;
            bf[ni][0] = Ks[n0 + kc * 8 + tg];
            bf[ni][1] = Ks[n0 + kc * 8 + 4 + tg];
        }
#pragma unroll
        for (int mi = 0; mi < 4; mi++)
#pragma unroll
            for (int ni = 0; ni < 4; ni++)
                mma_tf32(sacc[mi][ni], af[mi], bf[ni]);
    }

    // ---- stash K-hi
#pragma unroll
    for (int i = 0; i < 4; i++) {
        const int idx = i * 256 + t;
        const int r = idx >> 3, c4 = 32 + (idx & 7) * 4;
        uint32_t* dk = &Ks[r * 68 + c4];
        dk[0] = f2tf(pk[i].x); dk[1] = f2tf(pk[i].y);
        dk[2] = f2tf(pk[i].z); dk[3] = f2tf(pk[i].w);
    }
    __syncthreads();

    // ---- MMA on K-hi (kc 4-7)
#pragma unroll
    for (int kc = 4; kc < 8; kc++) {
        uint32_t af[4][4], bf[4][2];
#pragma unroll
        for (int mi = 0; mi < 4; mi++) {
            const int r0 = (m_half * 64 + mi * 16 + g) * 68;
            af[mi][0] = Qs[r0 + kc * 8 + tg];
            af[mi][1] = Qs[r0 + 8 * 68 + kc * 8 + tg];
            af[mi][2] = Qs[r0 + kc * 8 + 4 + tg];
            af[mi][3] = Qs[r0 + 8 * 68 + kc * 8 + 4 + tg];
        }
#pragma unroll
        for (int ni = 0; ni < 4; ni++) {
            const int n0 = (n_off + ni * 8 + g) * 68;
            bf[ni][0] = Ks[n0 + kc * 8 + tg];
            bf[ni][1] = Ks[n0 + kc * 8 + 4 + tg];
        }
#pragma unroll
        for (int mi = 0; mi < 4; mi++)
#pragma unroll
            for (int ni = 0; ni < 4; ni++)
                mma_tf32(sacc[mi][ni], af[mi], bf[ni]);
    }

    // scale
#pragma unroll
    for (int mi = 0; mi < 4; mi++)
#pragma unroll
        for (int ni = 0; ni < 4; ni++)
#pragma unroll
            for (int r = 0; r < 4; r++) sacc[mi][ni][r] *= 0.125f;

    // per-tile row max
#pragma unroll
    for (int mi = 0; mi < 4; mi++) {
        float v0 = -1e30f, v1 = -1e30f;
#pragma unroll
        for (int ni = 0; ni < 4; ni++) {
            v0 = fmaxf(v0, fmaxf(sacc[mi][ni][0], sacc[mi][ni][1]));
            v1 = fmaxf(v1, fmaxf(sacc[mi][ni][2], sacc[mi][ni][3]));
        }
        v0 = fmaxf(v0, __shfl_xor_sync(0xffffffffu, v0, 1));
        v0 = fmaxf(v0, __shfl_xor_sync(0xffffffffu, v0, 2));
        v1 = fmaxf(v1, __shfl_xor_sync(0xffffffffu, v1, 1));
        v1 = fmaxf(v1, __shfl_xor_sync(0xffffffffu, v1, 2));
        if (tg == 0) {
            wred[(m_half * 64 + mi * 16 + g) * 4 + nwarp]     = v0;
            wred[(m_half * 64 + mi * 16 + 8 + g) * 4 + nwarp] = v1;
        }
    }
    __syncthreads();
    if (t < 128) {
        mrow[t] = fmaxf(fmaxf(wred[t * 4], wred[t * 4 + 1]),
                        fmaxf(wred[t * 4 + 2], wred[t * 4 + 3]));
    }
    __syncthreads();

    // e = exp(s - m) (kept in sacc), row sum
#pragma unroll
    for (int mi = 0; mi < 4; mi++) {
        const float m0 = mrow[m_half * 64 + mi * 16 + g];
        const float m1 = mrow[m_half * 64 + mi * 16 + 8 + g];
        float s0 = 0.f, s1 = 0.f;
#pragma unroll
        for (int ni = 0; ni < 4; ni++) {
            sacc[mi][ni][0] = __expf(sacc[mi][ni][0] - m0);
            sacc[mi][ni][1] = __expf(sacc[mi][ni][1] - m0);
            sacc[mi][ni][2] = __expf(sacc[mi][ni][2] - m1);
            sacc[mi][ni][3] = __expf(sacc[mi][ni][3] - m1);
            s0 += sacc[mi][ni][0] + sacc[mi][ni][1];
            s1 += sacc[mi][ni][2] + sacc[mi][ni][3];
        }
        s0 += __shfl_xor_sync(0xffffffffu, s0, 1);
        s0 += __shfl_xor_sync(0xffffffffu, s0, 2);
        s1 += __shfl_xor_sync(0xffffffffu, s1, 1);
        s1 += __shfl_xor_sync(0xffffffffu, s1, 2);
        if (tg == 0) {
            wsum[(m_half * 64 + mi * 16 + g) * 4 + nwarp]     = s0;
            wsum[(m_half * 64 + mi * 16 + 8 + g) * 4 + nwarp] = s1;
        }
    }
    __syncthreads();
    if (t < 128) {
        float l = wsum[t * 4] + wsum[t * 4 + 1] + wsum[t * 4 + 2] + wsum[t * 4 + 3];
        float2* st = (float2*)(stats + (((long long)bh * Tc + qbase + t) * 16 + blockIdx.x) * 2);
        *st = make_float2(mrow[t], l);
    }

    // store e tile
#pragma unroll
    for (int mi = 0; mi < 4; mi++) {
#pragma unroll
        for (int ni = 0; ni < 4; ni++) {
            const int row = m_half * 64 + mi * 16 + g;
            const int col = nbase + n_off + ni * 8 + tg * 2;
            float* w0 = eout + ((long long)bh * Tc + qbase + row) * Tc + col;
            *(float2*)w0 = make_float2(sacc[mi][ni][0], sacc[mi][ni][1]);
            *(float2*)(w0 + 8 * Tc) = make_float2(sacc[mi][ni][2], sacc[mi][ni][3]);
        }
    }
}

// ---------------------------------------------------------------------------
// softmax+PV (software-pipelined): one CTA = 128 query rows of one (b,h).
// Iter sub: stash prefetched regs to smem (w STG + tf32 P/V STS), sync,
// prefetch sub+1 (LDGs overlap MMA), MMA, sync.  Exp-free stream loop.
// smem (words): Pp[128*68] @0, Vs[64*72] @8704, rsc[128*16] @13312
// ---------------------------------------------------------------------------
static constexpr int SPV_SMEM_BYTES = (8704 + 4608 + 2048) * 4;   // 61440 B

__global__ __launch_bounds__(256, 2) void softmax_pv(
    const float* __restrict__ v, float* __restrict__ w,
    const float* __restrict__ stats, float* __restrict__ attn)
{
    extern __shared__ uint32_t sm[];
    uint32_t* Pp = sm;
    uint32_t* Vs = sm + 8704;
    float*    rsc = (float*)(sm + 13312);     // [128][16]

    const int bh = blockIdx.z;
    const int b = bh >> 4, h = bh & 15;
    const int qbase = blockIdx.y * 128;
    const int t = threadIdx.x, warp = t >> 5, lane = t & 31;
    const int g = lane >> 2, tg = lane & 3;

    const float* vp = v + ((long long)b * Tc) * Dc + h * 64;
    float* wb = w + ((long long)bh * Tc + qbase) * Tc;

    // per-row final stats -> 16 per-tile rescale factors
    if (t < 128) {
        const float2* st = (const float2*)(stats + (((long long)bh * Tc + qbase + t) * 16) * 2);
        float2 sl[16];
        float m = -1e30f;
#pragma unroll
        for (int j = 0; j < 16; j++) { sl[j] = st[j]; m = fmaxf(m, sl[j].x); }
        float l = 0.f;
#pragma unroll
        for (int j = 0; j < 16; j++) l += sl[j].y * __expf(sl[j].x - m);
        const float inv = 1.0f / l;
#pragma unroll
        for (int j = 0; j < 16; j++) rsc[t * 16 + j] = __expf(sl[j].x - m) * inv;
    }

    // per-thread fixed addressing for the streamed strips
    const int erow = t >> 4;                  // 0..15 (x8 strips of 16 rows)
    const int ec4  = (t & 15) * 4;
    const int vrow = t >> 4;                  // 0..15 (x4 strips of 16 rows)
    const int vc4  = (t & 15) * 4;

    float4 pe[8], pv4[4];
    // prefetch sub = 0
#pragma unroll
    for (int i = 0; i < 4; i++)
        pv4[i] = *(const float4*)(vp + (long long)(i * 16 + vrow) * Dc + vc4);
#pragma unroll
    for (int i = 0; i < 8; i++)
        pe[i] = *(const float4*)(wb + (long long)(i * 16 + erow) * Tc + ec4);

    __syncthreads();   // rsc ready

    float oacc[8][4];
#pragma unroll
    for (int nf = 0; nf < 8; nf++)
#pragma unroll
        for (int r = 0; r < 4; r++) oacc[nf][r] = 0.f;

    for (int sub = 0; sub < 32; sub++) {
        const int j = sub >> 1;
        // ---- stash phase: V tf32 -> smem, e -> normalized w (STG) + tf32 P -> smem
#pragma unroll
        for (int i = 0; i < 4; i++) {
            uint32_t* d = &Vs[(i * 16 + vrow) * 72 + vc4];
            d[0] = f2tf(pv4[i].x); d[1] = f2tf(pv4[i].y);
            d[2] = f2tf(pv4[i].z); d[3] = f2tf(pv4[i].w);
        }
#pragma unroll
        for (int i = 0; i < 8; i++) {
            const int row = i * 16 + erow;
            const float sc = rsc[row * 16 + j];
            float4 p = make_float4(pe[i].x * sc, pe[i].y * sc, pe[i].z * sc, pe[i].w * sc);
            *(float4*)(wb + (long long)row * Tc + sub * 64 + ec4) = p;
            uint32_t* d = &Pp[row * 68 + ec4];
            d[0] = f2tf(p.x); d[1] = f2tf(p.y); d[2] = f2tf(p.z); d[3] = f2tf(p.w);
        }
        __syncthreads();

        // ---- prefetch sub+1 (LDGs overlap the MMA below)
        if (sub < 31) {
            const float* vpn = vp + (long long)(sub + 1) * 64 * Dc;
            const float* wbn = wb + (sub + 1) * 64;
#pragma unroll
            for (int i = 0; i < 4; i++)
                pv4[i] = *(const float4*)(vpn + (long long)(i * 16 + vrow) * Dc + vc4);
#pragma unroll
            for (int i = 0; i < 8; i++)
                pe[i] = *(const float4*)(wbn + (long long)(i * 16 + erow) * Tc + ec4);
        }

        // ---- O += P @ V
#pragma unroll
        for (int kc = 0; kc < 8; kc++) {
            const int r0 = (warp * 16 + g) * 68;
            uint32_t a[4];
            a[0] = Pp[r0 + kc * 8 + tg];
            a[1] = Pp[r0 + 8 * 68 + kc * 8 + tg];
            a[2] = Pp[r0 + kc * 8 + 4 + tg];
            a[3] = Pp[r0 + 8 * 68 + kc * 8 + 4 + tg];
#pragma unroll
            for (int nf = 0; nf < 8; nf++) {
                uint32_t bfr[2];
                bfr[0] = Vs[(kc * 8 + tg) * 72 + nf * 8 + g];
                bfr[1] = Vs[(kc * 8 + 4 + tg) * 72 + nf * 8 + g];
                mma_tf32(oacc[nf], a, bfr);
            }
        }
        __syncthreads();
    }

    // write O into attn buffer [B,T,D]
    float* op0 = attn + ((long long)(b * Tc + qbase + warp * 16 + g)) * Dc + h * 64;
    float* op1 = op0 + 8 * Dc;
#pragma unroll
    for (int nf = 0; nf < 8; nf++) {
        const int c = nf * 8 + tg * 2;
        *(float2*)(op0 + c) = make_float2(oacc[nf][0], oacc[nf][1]);
        *(float2*)(op1 + c) = make_float2(oacc[nf][2], oacc[nf][3]);
    }
}

// ---------------------------------------------------------------------------
extern "C" void kernel_launch(void* const* d_in, const int* /*in_sizes*/, int /*n_in*/,
                              void* d_out, int out_size)
{
    const float* query = (const float*)d_in[0];
    const float* key_i = (const float*)d_in[1];
    const float* value = (const float*)d_in[2];
    const float* Wq    = (const float*)d_in[3];
    const float* Wk    = (const float*)d_in[4];
    const float* Wv    = (const float*)d_in[5];
    const float* Wo    = (const float*)d_in[6];
    float* out = (float*)d_out;

    float *q, *k, *v, *attn, *stats, *wbuf;
    cudaGetSymbolAddress((void**)&q,     g_q);
    cudaGetSymbolAddress((void**)&k,     g_k);
    cudaGetSymbolAddress((void**)&v,     g_v);
    cudaGetSymbolAddress((void**)&attn,  g_attn);
    cudaGetSymbolAddress((void**)&stats, g_stats);
    if ((long long)out_size >= OUT_ELEMS + W_ELEMS) {
        wbuf = out + OUT_ELEMS;                 // tuple-concat output: [out | weights]
    } else {
        cudaGetSymbolAddress((void**)&wbuf, g_weights);
    }

    cudaFuncSetAttribute(proj_nt, cudaFuncAttributeMaxDynamicSharedMemorySize,
                         PROJ_SMEM_BYTES);
    cudaFuncSetAttribute(scores_kernel, cudaFuncAttributeMaxDynamicSharedMemorySize,
                         SC_SMEM_BYTES);
    cudaFuncSetAttribute(softmax_pv, cudaFuncAttributeMaxDynamicSharedMemorySize,
                         SPV_SMEM_BYTES);

    // 1) Q/K/V projections in one launch (double-buffered)
    proj_nt<<<dim3(8, 32, 3), 256, PROJ_SMEM_BYTES>>>(query, Wq, q, key_i, Wk, k, value, Wv, v);

    // 2) e = exp(s - m_tile) + per-tile stats (split-K pipelined)
    scores_kernel<<<dim3(16, 16, 32), 256, SC_SMEM_BYTES>>>(q, k, wbuf, stats);

    // 3) rescale to final weights (in place) + PV (pipelined)
    softmax_pv<<<dim3(1, 16, 32), 256, SPV_SMEM_BYTES>>>(v, wbuf, stats, attn);

    // 4) out = attn @ Wo^T (double-buffered)
    proj_nt<<<dim3(8, 32, 1), 256, PROJ_SMEM_BYTES>>>(attn, Wo, out, attn, Wo, out, attn, Wo, out);
}